// round 13
// baseline (speedup 1.0000x reference)
#include <cuda_runtime.h>
#include <cstdint>

#define B_  64
#define T_  2048
#define I_  128
#define H_  256
#define C_  64
#define G3  (3 * H_)   // 768

__device__ float g_gates[(size_t)B_ * T_ * G3];
__device__ float g_h[(size_t)B_ * T_ * H_];

// ---------------------------------------------------------------------------
// helpers
// ---------------------------------------------------------------------------
__device__ __forceinline__ float tanh_hw_(float x) {
    float r;
    asm("tanh.approx.f32 %0, %1;" : "=f"(r) : "f"(x));
    return r;
}
__device__ __forceinline__ float sigmoid_hw_(float x) {
    return fmaf(0.5f, tanh_hw_(0.5f * x), 0.5f);
}
__device__ __forceinline__ void fma2_(uint64_t& d, uint64_t a, uint64_t b) {
    asm("fma.rn.f32x2 %0, %1, %2, %0;" : "+l"(d) : "l"(a), "l"(b));
}
__device__ __forceinline__ float f2lo_(uint64_t v) {
    float lo, hi;
    asm("mov.b64 {%0,%1}, %2;" : "=f"(lo), "=f"(hi) : "l"(v));
    return lo;
}
__device__ __forceinline__ float f2hi_(uint64_t v) {
    float lo, hi;
    asm("mov.b64 {%0,%1}, %2;" : "=f"(lo), "=f"(hi) : "l"(v));
    return hi;
}
__device__ __forceinline__ uint64_t dup2_(float x) {
    uint64_t r;
    asm("mov.b64 %0, {%1,%1};" : "=l"(r) : "f"(x));
    return r;
}
__device__ __forceinline__ void mbar_init_(uint32_t a, uint32_t cnt) {
    asm volatile("mbarrier.init.shared.b64 [%0], %1;" :: "r"(a), "r"(cnt) : "memory");
}
__device__ __forceinline__ void mbar_arm_(uint32_t a, uint32_t tx) {
    asm volatile("mbarrier.arrive.expect_tx.shared.b64 _, [%0], %1;"
                 :: "r"(a), "r"(tx) : "memory");
}
__device__ __forceinline__ void mbar_wait_(uint32_t a, uint32_t par) {
    uint32_t done;
    asm volatile(
        "{\n\t.reg .pred p;\n\t"
        "mbarrier.try_wait.parity.acquire.cta.shared::cta.b64 p, [%1], %2;\n\t"
        "selp.b32 %0, 1, 0, p;\n\t}"
        : "=r"(done) : "r"(a), "r"(par) : "memory");
    if (!done) {
        asm volatile(
            "{\n\t.reg .pred P1;\n\t"
            "W_%=:\n\t"
            "mbarrier.try_wait.parity.acquire.cta.shared::cta.b64 P1, [%0], %1, 0x989680;\n\t"
            "@P1 bra.uni D_%=;\n\t"
            "bra.uni W_%=;\n\t"
            "D_%=:\n\t}"
            :: "r"(a), "r"(par) : "memory");
    }
}

// ---------------------------------------------------------------------------
// GEMM: C[m,n] = sum_k A[m,k] * B[n,k] + bias[n]
// BM=128, BN=64, BK=32 (halved sync count vs R11), 256 threads, f32x2 inner,
// double-buffered. k-order inside the accumulation is unchanged ->
// bit-identical results to the BK=16 version.
// ---------------------------------------------------------------------------
__global__ void __launch_bounds__(256) gemm_nt(
    const float* __restrict__ A, const float* __restrict__ Bm,
    const float* __restrict__ bias, float* __restrict__ C,
    int M, int N, int K)
{
    const int BM = 128, BN = 64, BK = 32;
    __shared__ float As[2][BK * BM];
    __shared__ float Bs[2][BK * BN];

    int tid = threadIdx.x;
    int tx = tid & 15;
    int ty = tid >> 4;
    int m0 = blockIdx.y * BM;
    int n0 = blockIdx.x * BN;

    const int rowb = tid >> 3;     // 0..31
    const int c8   = tid & 7;      // float4 column group (cols c8*4..c8*4+3)

    uint64_t acc2[4][4];
#pragma unroll
    for (int i = 0; i < 4; i++)
#pragma unroll
        for (int j = 0; j < 4; j++) acc2[i][j] = 0ull;

    float4 a_stg[4], b_stg[2];

    // load tile 0
#pragma unroll
    for (int i = 0; i < 4; i++)
        a_stg[i] = *(const float4*)&A[(size_t)(m0 + rowb + 32 * i) * K + c8 * 4];
#pragma unroll
    for (int i = 0; i < 2; i++)
        b_stg[i] = *(const float4*)&Bm[(size_t)(n0 + rowb + 32 * i) * K + c8 * 4];
    {
        float* as = As[0]; float* bs = Bs[0];
#pragma unroll
        for (int i = 0; i < 4; i++) {
            int row = rowb + 32 * i;
            as[(c8 * 4 + 0) * BM + row] = a_stg[i].x;
            as[(c8 * 4 + 1) * BM + row] = a_stg[i].y;
            as[(c8 * 4 + 2) * BM + row] = a_stg[i].z;
            as[(c8 * 4 + 3) * BM + row] = a_stg[i].w;
        }
#pragma unroll
        for (int i = 0; i < 2; i++) {
            int row = rowb + 32 * i;
            bs[(c8 * 4 + 0) * BN + row] = b_stg[i].x;
            bs[(c8 * 4 + 1) * BN + row] = b_stg[i].y;
            bs[(c8 * 4 + 2) * BN + row] = b_stg[i].z;
            bs[(c8 * 4 + 3) * BN + row] = b_stg[i].w;
        }
    }
    __syncthreads();

    int p = 0;
    for (int kt = 0; kt < K; kt += BK) {
        const bool has_next = (kt + BK) < K;
        if (has_next) {
#pragma unroll
            for (int i = 0; i < 4; i++)
                a_stg[i] = *(const float4*)&A[(size_t)(m0 + rowb + 32 * i) * K + kt + BK + c8 * 4];
#pragma unroll
            for (int i = 0; i < 2; i++)
                b_stg[i] = *(const float4*)&Bm[(size_t)(n0 + rowb + 32 * i) * K + kt + BK + c8 * 4];
        }

        const float* as = As[p];
        const float* bs = Bs[p];
#pragma unroll
        for (int k = 0; k < BK; k++) {
            const uint64_t* a2 = (const uint64_t*)&as[k * BM + ty * 8];
            uint64_t av0 = a2[0], av1 = a2[1], av2 = a2[2], av3 = a2[3];
            float4 bq = *(const float4*)&bs[k * BN + tx * 4];
            uint64_t b0 = dup2_(bq.x), b1 = dup2_(bq.y);
            uint64_t b2 = dup2_(bq.z), b3 = dup2_(bq.w);
            fma2_(acc2[0][0], av0, b0); fma2_(acc2[0][1], av0, b1);
            fma2_(acc2[0][2], av0, b2); fma2_(acc2[0][3], av0, b3);
            fma2_(acc2[1][0], av1, b0); fma2_(acc2[1][1], av1, b1);
            fma2_(acc2[1][2], av1, b2); fma2_(acc2[1][3], av1, b3);
            fma2_(acc2[2][0], av2, b0); fma2_(acc2[2][1], av2, b1);
            fma2_(acc2[2][2], av2, b2); fma2_(acc2[2][3], av2, b3);
            fma2_(acc2[3][0], av3, b0); fma2_(acc2[3][1], av3, b1);
            fma2_(acc2[3][2], av3, b2); fma2_(acc2[3][3], av3, b3);
        }

        if (has_next) {
            float* asn = As[p ^ 1]; float* bsn = Bs[p ^ 1];
#pragma unroll
            for (int i = 0; i < 4; i++) {
                int row = rowb + 32 * i;
                asn[(c8 * 4 + 0) * BM + row] = a_stg[i].x;
                asn[(c8 * 4 + 1) * BM + row] = a_stg[i].y;
                asn[(c8 * 4 + 2) * BM + row] = a_stg[i].z;
                asn[(c8 * 4 + 3) * BM + row] = a_stg[i].w;
            }
#pragma unroll
            for (int i = 0; i < 2; i++) {
                int row = rowb + 32 * i;
                bsn[(c8 * 4 + 0) * BN + row] = b_stg[i].x;
                bsn[(c8 * 4 + 1) * BN + row] = b_stg[i].y;
                bsn[(c8 * 4 + 2) * BN + row] = b_stg[i].z;
                bsn[(c8 * 4 + 3) * BN + row] = b_stg[i].w;
            }
            __syncthreads();
        }
        p ^= 1;
    }

    float4 bv = *(const float4*)&bias[n0 + tx * 4];
#pragma unroll
    for (int ii = 0; ii < 4; ii++) {
        float4 oe, oo;
        oe.x = f2lo_(acc2[ii][0]) + bv.x;
        oe.y = f2lo_(acc2[ii][1]) + bv.y;
        oe.z = f2lo_(acc2[ii][2]) + bv.z;
        oe.w = f2lo_(acc2[ii][3]) + bv.w;
        oo.x = f2hi_(acc2[ii][0]) + bv.x;
        oo.y = f2hi_(acc2[ii][1]) + bv.y;
        oo.z = f2hi_(acc2[ii][2]) + bv.z;
        oo.w = f2hi_(acc2[ii][3]) + bv.w;
        *(float4*)&C[(size_t)(m0 + ty * 8 + 2 * ii) * N + n0 + tx * 4] = oe;
        *(float4*)&C[(size_t)(m0 + ty * 8 + 2 * ii + 1) * N + n0 + tx * 4] = oo;
    }
}

// ---------------------------------------------------------------------------
// GRU recurrent scan — R11 structure verbatim (proven fastest), one delta:
// the epilogue carries h in a register (hold == this thread's previous hnew,
// static mapping) instead of re-loading it from SMEM. Bit-identical.
// ---------------------------------------------------------------------------
#define HQ_HALF 260
#define HQ_P    (2 * HQ_HALF)   // 520 floats per phase buffer
#define TXB     2048u           // 4 sources * 512B per CTA per step

__global__ void __cluster_dims__(4, 1, 1) __launch_bounds__(384, 1)
gru_scan(const float* __restrict__ gates, const float* __restrict__ Whh,
         const float* __restrict__ bhh, float* __restrict__ hout)
{
    __shared__ __align__(16) float hq[2 * HQ_P];
    __shared__ __align__(16) float stag[2][128];   // staging, per phase
    __shared__ float gh_s[2 * 192];                // [b][row]
    __shared__ float bh_s[192];
    __shared__ __align__(8) uint64_t mbar_s[2];

    int tid = threadIdx.x;
    uint32_t rank;
    asm("mov.u32 %0, %%cluster_ctarank;" : "=r"(rank));
    int b0 = (blockIdx.x >> 2) * 2;

    const int row = tid >> 1;          // 0..191 = g*64 + jl
    const int ks  = tid & 1;
    const int g   = row >> 6;
    const int jl  = row & 63;
    const int grow = g * H_ + (int)rank * 64 + jl;

    // W_hh row-half -> 64 packed b64 registers (once).
    uint64_t wr[64];
    const uint64_t* wsrc = (const uint64_t*)&Whh[(size_t)grow * H_ + ks * 128];
#pragma unroll
    for (int kk = 0; kk < 64; kk++) wr[kk] = wsrc[kk];

    uint32_t hq_u32   = (uint32_t)__cvta_generic_to_shared(hq);
    uint32_t stag_u32 = (uint32_t)__cvta_generic_to_shared(stag);
    uint32_t mbar_u32 = (uint32_t)__cvta_generic_to_shared(mbar_s);

    if (tid < 192) {
        int gg = tid >> 6, jj = tid & 63;
        bh_s[tid] = bhh[gg * H_ + (int)rank * 64 + jj];
    }
    for (int i = tid; i < 2 * HQ_P; i += 384) hq[i] = 0.0f;
    if (tid == 0) {
        mbar_init_(mbar_u32, 1);
        mbar_init_(mbar_u32 + 8, 1);
        mbar_arm_(mbar_u32 + 8, TXB);   // arm mbar[1] for step-0 sends
    }
    __syncthreads();
    asm volatile("barrier.cluster.arrive.aligned;" ::: "memory");
    asm volatile("barrier.cluster.wait.aligned;" ::: "memory");

    const uint32_t ks_off = (uint32_t)ks * (HQ_HALF * 4);

    // Epilogue mapping (threads 0..127): batch bb, local column jl_e.
    const int jl_e = tid & 63;
    const int bb   = (tid >> 6) & 1;
    const int jg   = (int)rank * 64 + jl_e;
    // staging slot: quad per local pair {b0_2k, b0_2k+1, b1_2k, b1_2k+1}
    const int sidx = ((jl_e >> 1) << 2) + bb * 2 + (jl_e & 1);
    // destination byte offset of this rank's slice inside a phase buffer
    const uint32_t dst_off = (rank >> 1) * (HQ_HALF * 4) + (rank & 1) * 512;

    float hprev = 0.0f;   // register-carried h for this thread's (bb, jg)

    uint32_t ph = 0;   // parity bits for mbar[0], mbar[1]
    for (int t = 0; t < T_; t++) {
        const int buf = t & 1;
        const int nxt = buf ^ 1;

        // Prefetch gates_x (independent of h).
        float xr = 0.f, xz = 0.f, xn = 0.f;
        if (tid < 128) {
            const float* gp = &gates[((size_t)(b0 + bb) * T_ + t) * G3];
            xr = __ldg(gp + jg);
            xz = __ldg(gp + 256 + jg);
            xn = __ldg(gp + 512 + jg);
        }

        if (t) {
            mbar_wait_(mbar_u32 + buf * 8, (ph >> buf) & 1u);
            ph ^= (1u << buf);
        }
        // Re-arm this buffer's barrier for step t+2.
        if (tid == 0) mbar_arm_(mbar_u32 + buf * 8, TXB);

        // Fused matvec, both batches.
        uint32_t hb = hq_u32 + (uint32_t)buf * (HQ_P * 4) + ks_off;
        uint64_t a00 = 0, a01 = 0, a10 = 0, a11 = 0;
#pragma unroll
        for (int kk = 0; kk < 64; kk += 2) {
            uint64_t hx0, hy0, hx1, hy1;
            asm volatile("ld.shared.v2.u64 {%0,%1}, [%2];"
                         : "=l"(hx0), "=l"(hy0) : "r"(hb + kk * 16));
            asm volatile("ld.shared.v2.u64 {%0,%1}, [%2];"
                         : "=l"(hx1), "=l"(hy1) : "r"(hb + kk * 16 + 16));
            fma2_(a00, wr[kk], hx0);
            fma2_(a10, wr[kk], hy0);
            fma2_(a01, wr[kk + 1], hx1);
            fma2_(a11, wr[kk + 1], hy1);
        }
        float s0 = (f2lo_(a00) + f2hi_(a00)) + (f2lo_(a01) + f2hi_(a01));
        float s1 = (f2lo_(a10) + f2hi_(a10)) + (f2lo_(a11) + f2hi_(a11));
        s0 += __shfl_xor_sync(0xffffffffu, s0, 1);
        s1 += __shfl_xor_sync(0xffffffffu, s1, 1);
        if (ks == 0) {
            float bh = bh_s[row];
            gh_s[row]       = s0 + bh;
            gh_s[192 + row] = s1 + bh;
        }
        __syncthreads();

        if (tid < 128) {
            float r = sigmoid_hw_(xr + gh_s[bb * 192 + jl_e]);
            float z = sigmoid_hw_(xz + gh_s[bb * 192 + 64 + jl_e]);
            float n = tanh_hw_(xn + r * gh_s[bb * 192 + 128 + jl_e]);
            float hnew = (1.0f - z) * n + z * hprev;
            hprev = hnew;

            stag[nxt][sidx] = hnew;
            hout[((size_t)(b0 + bb) * T_ + t) * H_ + jg] = hnew;

            // All staging writes visible, then lanes 0-3 each bulk-send the
            // 512B slice to one CTA of the cluster (tc = tid).
            asm volatile("bar.sync 1, 128;" ::: "memory");
            if (tid < 4) {
                asm volatile("fence.proxy.async.shared::cta;" ::: "memory");
                uint32_t src = stag_u32 + (uint32_t)nxt * 512;
                uint32_t dst = hq_u32 + (uint32_t)nxt * (HQ_P * 4) + dst_off;
                uint32_t mb  = mbar_u32 + nxt * 8;
                asm volatile(
                    "{\n\t.reg .b32 ra, rb;\n\t"
                    "mapa.shared::cluster.u32 ra, %0, %3;\n\t"
                    "mapa.shared::cluster.u32 rb, %1, %3;\n\t"
                    "cp.async.bulk.shared::cluster.shared::cta."
                    "mbarrier::complete_tx::bytes [ra], [%2], 512, [rb];\n\t}"
                    :: "r"(dst), "r"(mb), "r"(src), "r"((uint32_t)tid) : "memory");
            }
        }
        // Warps 4-11 fall straight through to the next wait.
    }

    // Drain inbound copies before exit.
    mbar_wait_(mbar_u32, ph & 1u);
    asm volatile("barrier.cluster.arrive.aligned;" ::: "memory");
    asm volatile("barrier.cluster.wait.aligned;" ::: "memory");
}

// ---------------------------------------------------------------------------
extern "C" void kernel_launch(void* const* d_in, const int* in_sizes, int n_in,
                              void* d_out, int out_size)
{
    const float* x    = (const float*)d_in[0];
    const float* Wih0 = (const float*)d_in[1];
    const float* Whh0 = (const float*)d_in[2];
    const float* bih0 = (const float*)d_in[3];
    const float* bhh0 = (const float*)d_in[4];
    const float* Wih1 = (const float*)d_in[5];
    const float* Whh1 = (const float*)d_in[6];
    const float* bih1 = (const float*)d_in[7];
    const float* bhh1 = (const float*)d_in[8];
    const float* fcw  = (const float*)d_in[9];
    const float* fcb  = (const float*)d_in[10];
    float* out = (float*)d_out;

    float *gates, *h;
    cudaGetSymbolAddress((void**)&gates, g_gates);
    cudaGetSymbolAddress((void**)&h, g_h);

    const int M = B_ * T_;
    dim3 blk(256);

    gemm_nt<<<dim3(G3 / 64, M / 128), blk>>>(x, Wih0, bih0, gates, M, G3, I_);
    gru_scan<<<128, 384>>>(gates, Whh0, bhh0, h);

    gemm_nt<<<dim3(G3 / 64, M / 128), blk>>>(h, Wih1, bih1, gates, M, G3, H_);
    gru_scan<<<128, 384>>>(gates, Whh1, bhh1, h);

    gemm_nt<<<dim3(C_ / 64, M / 128), blk>>>(h, fcw, fcb, out, M, C_, H_);
}

// round 15
// speedup vs baseline: 1.1229x; 1.1229x over previous
#include <cuda_runtime.h>
#include <cuda_bf16.h>
#include <mma.h>
#include <cstdint>

using namespace nvcuda;

#define B_  64
#define T_  2048
#define I_  128
#define H_  256
#define C_  64
#define G3  (3 * H_)   // 768

__device__ float g_gates[(size_t)B_ * T_ * G3];
__device__ float g_h[(size_t)B_ * T_ * H_];

// ---------------------------------------------------------------------------
// helpers
// ---------------------------------------------------------------------------
__device__ __forceinline__ float tanh_hw_(float x) {
    float r;
    asm("tanh.approx.f32 %0, %1;" : "=f"(r) : "f"(x));
    return r;
}
__device__ __forceinline__ float sigmoid_hw_(float x) {
    return fmaf(0.5f, tanh_hw_(0.5f * x), 0.5f);
}
__device__ __forceinline__ void fma2_(uint64_t& d, uint64_t a, uint64_t b) {
    asm("fma.rn.f32x2 %0, %1, %2, %0;" : "+l"(d) : "l"(a), "l"(b));
}
__device__ __forceinline__ float f2lo_(uint64_t v) {
    float lo, hi;
    asm("mov.b64 {%0,%1}, %2;" : "=f"(lo), "=f"(hi) : "l"(v));
    return lo;
}
__device__ __forceinline__ float f2hi_(uint64_t v) {
    float lo, hi;
    asm("mov.b64 {%0,%1}, %2;" : "=f"(lo), "=f"(hi) : "l"(v));
    return hi;
}
__device__ __forceinline__ uint64_t dup2_(float x) {
    uint64_t r;
    asm("mov.b64 %0, {%1,%1};" : "=l"(r) : "f"(x));
    return r;
}
__device__ __forceinline__ void mbar_init_(uint32_t a, uint32_t cnt) {
    asm volatile("mbarrier.init.shared.b64 [%0], %1;" :: "r"(a), "r"(cnt) : "memory");
}
__device__ __forceinline__ void mbar_arm_(uint32_t a, uint32_t tx) {
    asm volatile("mbarrier.arrive.expect_tx.shared.b64 _, [%0], %1;"
                 :: "r"(a), "r"(tx) : "memory");
}
__device__ __forceinline__ void mbar_wait_(uint32_t a, uint32_t par) {
    uint32_t done;
    asm volatile(
        "{\n\t.reg .pred p;\n\t"
        "mbarrier.try_wait.parity.acquire.cta.shared::cta.b64 p, [%1], %2;\n\t"
        "selp.b32 %0, 1, 0, p;\n\t}"
        : "=r"(done) : "r"(a), "r"(par) : "memory");
    if (!done) {
        asm volatile(
            "{\n\t.reg .pred P1;\n\t"
            "W_%=:\n\t"
            "mbarrier.try_wait.parity.acquire.cta.shared::cta.b64 P1, [%0], %1, 0x989680;\n\t"
            "@P1 bra.uni D_%=;\n\t"
            "bra.uni W_%=;\n\t"
            "D_%=:\n\t}"
            :: "r"(a), "r"(par) : "memory");
    }
}

__device__ __forceinline__ void sthl_(__nv_bfloat16* Hh, __nv_bfloat16* Hl,
                                      int idx, float x) {
    __nv_bfloat16 h = __float2bfloat16(x);
    Hh[idx] = h;
    Hl[idx] = __float2bfloat16(x - __bfloat162float(h));
}

// ---------------------------------------------------------------------------
// wmma bf16-split GEMM: C[m,n] = sum_k A[m,k]*W[n,k] + bias[n] (fp32 I/O).
// D = Ah*Wh + Ah*Wl + Al*Wh, fp32 accumulators (rel err ~2^-17).
// CTA: 128x64 tile, 256 threads (8 warps, each a 32x32 patch = 2x2 frags).
// K staged 16/step as hi/lo bf16 SMEM tiles (stride 24 elems).
// ---------------------------------------------------------------------------
#define WST 24                       // smem tile stride (bf16 elems)
#define GW_SMEM (128 * 72 * 4)       // output staging dominates (36864 B)

__global__ void __launch_bounds__(256) gemm_wmma(
    const float* __restrict__ A, const float* __restrict__ W,
    const float* __restrict__ bias, float* __restrict__ C,
    int N_total, int K)
{
    extern __shared__ char sm[];
    __nv_bfloat16* Ah = (__nv_bfloat16*)sm;            // 128*24
    __nv_bfloat16* Al = Ah + 128 * WST;
    __nv_bfloat16* Bh = Al + 128 * WST;                // 64*24
    __nv_bfloat16* Bl = Bh + 64 * WST;
    float* Cst = (float*)sm;                           // reused post-loop

    const int tid = threadIdx.x;
    const int wid = tid >> 5;
    const int m0 = blockIdx.y * 128;
    const int n0 = blockIdx.x * 64;
    const int mh = (wid & 3) * 32;
    const int nh = (wid >> 2) * 32;

    wmma::fragment<wmma::accumulator, 16, 16, 16, float> acc[2][2];
#pragma unroll
    for (int i = 0; i < 2; i++)
#pragma unroll
        for (int j = 0; j < 2; j++) wmma::fill_fragment(acc[i][j], 0.0f);

    const int arow = tid >> 1, acol = (tid & 1) * 8;
    const int brow = tid >> 2, bcol = (tid & 3) * 4;

    for (int kt = 0; kt < K; kt += 16) {
        // stage A 128x16 (8 floats/thread) and W 64x16 (4 floats/thread)
        {
            const float* ap = &A[(size_t)(m0 + arow) * K + kt + acol];
            float4 v0 = *(const float4*)ap;
            float4 v1 = *(const float4*)(ap + 4);
            int base = arow * WST + acol;
            sthl_(Ah, Al, base + 0, v0.x); sthl_(Ah, Al, base + 1, v0.y);
            sthl_(Ah, Al, base + 2, v0.z); sthl_(Ah, Al, base + 3, v0.w);
            sthl_(Ah, Al, base + 4, v1.x); sthl_(Ah, Al, base + 5, v1.y);
            sthl_(Ah, Al, base + 6, v1.z); sthl_(Ah, Al, base + 7, v1.w);

            float4 w0 = *(const float4*)&W[(size_t)(n0 + brow) * K + kt + bcol];
            int bbase = brow * WST + bcol;
            sthl_(Bh, Bl, bbase + 0, w0.x); sthl_(Bh, Bl, bbase + 1, w0.y);
            sthl_(Bh, Bl, bbase + 2, w0.z); sthl_(Bh, Bl, bbase + 3, w0.w);
        }
        __syncthreads();

        wmma::fragment<wmma::matrix_a, 16, 16, 16, __nv_bfloat16, wmma::row_major> afh[2], afl[2];
        wmma::fragment<wmma::matrix_b, 16, 16, 16, __nv_bfloat16, wmma::col_major> bfh[2], bfl[2];
#pragma unroll
        for (int i = 0; i < 2; i++)
            wmma::load_matrix_sync(afh[i], &Ah[(mh + i * 16) * WST], WST);
#pragma unroll
        for (int j = 0; j < 2; j++)
            wmma::load_matrix_sync(bfh[j], &Bh[(nh + j * 16) * WST], WST);
#pragma unroll
        for (int i = 0; i < 2; i++)
#pragma unroll
            for (int j = 0; j < 2; j++)
                wmma::mma_sync(acc[i][j], afh[i], bfh[j], acc[i][j]);

#pragma unroll
        for (int j = 0; j < 2; j++)
            wmma::load_matrix_sync(bfl[j], &Bl[(nh + j * 16) * WST], WST);
#pragma unroll
        for (int i = 0; i < 2; i++)
#pragma unroll
            for (int j = 0; j < 2; j++)
                wmma::mma_sync(acc[i][j], afh[i], bfl[j], acc[i][j]);

#pragma unroll
        for (int i = 0; i < 2; i++)
            wmma::load_matrix_sync(afl[i], &Al[(mh + i * 16) * WST], WST);
#pragma unroll
        for (int i = 0; i < 2; i++)
#pragma unroll
            for (int j = 0; j < 2; j++)
                wmma::mma_sync(acc[i][j], afl[i], bfh[j], acc[i][j]);

        __syncthreads();   // fragments consumed; safe to restage
    }

    // stage accumulators, add bias, write out
#pragma unroll
    for (int i = 0; i < 2; i++)
#pragma unroll
        for (int j = 0; j < 2; j++)
            wmma::store_matrix_sync(&Cst[(mh + i * 16) * 72 + nh + j * 16],
                                    acc[i][j], 72, wmma::mem_row_major);
    __syncthreads();

    const int orow = tid >> 1;
    const int ocol = (tid & 1) * 32;
    float* crow = &C[(size_t)(m0 + orow) * N_total + n0 + ocol];
    const float* srow = &Cst[orow * 72 + ocol];
#pragma unroll
    for (int c = 0; c < 32; c += 4) {
        float4 o;
        o.x = srow[c]     + __ldg(&bias[n0 + ocol + c]);
        o.y = srow[c + 1] + __ldg(&bias[n0 + ocol + c + 1]);
        o.z = srow[c + 2] + __ldg(&bias[n0 + ocol + c + 2]);
        o.w = srow[c + 3] + __ldg(&bias[n0 + ocol + c + 3]);
        *(float4*)&crow[c] = o;
    }
}

// ---------------------------------------------------------------------------
// fp32 GEMM (R11 verbatim, BK=16, f32x2 inner) — used for the FC head.
// ---------------------------------------------------------------------------
__global__ void __launch_bounds__(256) gemm_nt(
    const float* __restrict__ A, const float* __restrict__ Bm,
    const float* __restrict__ bias, float* __restrict__ C,
    int M, int N, int K)
{
    const int BM = 128, BN = 64, BK = 16;
    __shared__ float As[2][BK * BM];
    __shared__ float Bs[2][BK * BN];

    int tid = threadIdx.x;
    int tx = tid & 15;
    int ty = tid >> 4;
    int m0 = blockIdx.y * BM;
    int n0 = blockIdx.x * BN;

    const int a_row0 = tid >> 2, a_c4 = tid & 3;
    const int b_row  = tid >> 2, b_c4 = tid & 3;

    uint64_t acc2[4][4];
#pragma unroll
    for (int i = 0; i < 4; i++)
#pragma unroll
        for (int j = 0; j < 4; j++) acc2[i][j] = 0ull;

    float4 a_stg0, a_stg1, b_stg;

    a_stg0 = *(const float4*)&A[(size_t)(m0 + a_row0) * K + a_c4 * 4];
    a_stg1 = *(const float4*)&A[(size_t)(m0 + a_row0 + 64) * K + a_c4 * 4];
    b_stg  = *(const float4*)&Bm[(size_t)(n0 + b_row) * K + b_c4 * 4];
    {
        float* as = As[0]; float* bs = Bs[0];
        as[(a_c4 * 4 + 0) * BM + a_row0] = a_stg0.x;
        as[(a_c4 * 4 + 1) * BM + a_row0] = a_stg0.y;
        as[(a_c4 * 4 + 2) * BM + a_row0] = a_stg0.z;
        as[(a_c4 * 4 + 3) * BM + a_row0] = a_stg0.w;
        as[(a_c4 * 4 + 0) * BM + a_row0 + 64] = a_stg1.x;
        as[(a_c4 * 4 + 1) * BM + a_row0 + 64] = a_stg1.y;
        as[(a_c4 * 4 + 2) * BM + a_row0 + 64] = a_stg1.z;
        as[(a_c4 * 4 + 3) * BM + a_row0 + 64] = a_stg1.w;
        bs[(b_c4 * 4 + 0) * BN + b_row] = b_stg.x;
        bs[(b_c4 * 4 + 1) * BN + b_row] = b_stg.y;
        bs[(b_c4 * 4 + 2) * BN + b_row] = b_stg.z;
        bs[(b_c4 * 4 + 3) * BN + b_row] = b_stg.w;
    }
    __syncthreads();

    int p = 0;
    for (int kt = 0; kt < K; kt += BK) {
        const bool has_next = (kt + BK) < K;
        if (has_next) {
            a_stg0 = *(const float4*)&A[(size_t)(m0 + a_row0) * K + kt + BK + a_c4 * 4];
            a_stg1 = *(const float4*)&A[(size_t)(m0 + a_row0 + 64) * K + kt + BK + a_c4 * 4];
            b_stg  = *(const float4*)&Bm[(size_t)(n0 + b_row) * K + kt + BK + b_c4 * 4];
        }

        const float* as = As[p];
        const float* bs = Bs[p];
#pragma unroll
        for (int k = 0; k < BK; k++) {
            const uint64_t* a2 = (const uint64_t*)&as[k * BM + ty * 8];
            uint64_t av0 = a2[0], av1 = a2[1], av2 = a2[2], av3 = a2[3];
            float4 bq = *(const float4*)&bs[k * BN + tx * 4];
            uint64_t b0 = dup2_(bq.x), b1 = dup2_(bq.y);
            uint64_t b2 = dup2_(bq.z), b3 = dup2_(bq.w);
            fma2_(acc2[0][0], av0, b0); fma2_(acc2[0][1], av0, b1);
            fma2_(acc2[0][2], av0, b2); fma2_(acc2[0][3], av0, b3);
            fma2_(acc2[1][0], av1, b0); fma2_(acc2[1][1], av1, b1);
            fma2_(acc2[1][2], av1, b2); fma2_(acc2[1][3], av1, b3);
            fma2_(acc2[2][0], av2, b0); fma2_(acc2[2][1], av2, b1);
            fma2_(acc2[2][2], av2, b2); fma2_(acc2[2][3], av2, b3);
            fma2_(acc2[3][0], av3, b0); fma2_(acc2[3][1], av3, b1);
            fma2_(acc2[3][2], av3, b2); fma2_(acc2[3][3], av3, b3);
        }

        if (has_next) {
            float* asn = As[p ^ 1]; float* bsn = Bs[p ^ 1];
            asn[(a_c4 * 4 + 0) * BM + a_row0] = a_stg0.x;
            asn[(a_c4 * 4 + 1) * BM + a_row0] = a_stg0.y;
            asn[(a_c4 * 4 + 2) * BM + a_row0] = a_stg0.z;
            asn[(a_c4 * 4 + 3) * BM + a_row0] = a_stg0.w;
            asn[(a_c4 * 4 + 0) * BM + a_row0 + 64] = a_stg1.x;
            asn[(a_c4 * 4 + 1) * BM + a_row0 + 64] = a_stg1.y;
            asn[(a_c4 * 4 + 2) * BM + a_row0 + 64] = a_stg1.z;
            asn[(a_c4 * 4 + 3) * BM + a_row0 + 64] = a_stg1.w;
            bsn[(b_c4 * 4 + 0) * BN + b_row] = b_stg.x;
            bsn[(b_c4 * 4 + 1) * BN + b_row] = b_stg.y;
            bsn[(b_c4 * 4 + 2) * BN + b_row] = b_stg.z;
            bsn[(b_c4 * 4 + 3) * BN + b_row] = b_stg.w;
            __syncthreads();
        }
        p ^= 1;
    }

    float4 bv = *(const float4*)&bias[n0 + tx * 4];
#pragma unroll
    for (int ii = 0; ii < 4; ii++) {
        float4 oe, oo;
        oe.x = f2lo_(acc2[ii][0]) + bv.x;
        oe.y = f2lo_(acc2[ii][1]) + bv.y;
        oe.z = f2lo_(acc2[ii][2]) + bv.z;
        oe.w = f2lo_(acc2[ii][3]) + bv.w;
        oo.x = f2hi_(acc2[ii][0]) + bv.x;
        oo.y = f2hi_(acc2[ii][1]) + bv.y;
        oo.z = f2hi_(acc2[ii][2]) + bv.z;
        oo.w = f2hi_(acc2[ii][3]) + bv.w;
        *(float4*)&C[(size_t)(m0 + ty * 8 + 2 * ii) * N + n0 + tx * 4] = oe;
        *(float4*)&C[(size_t)(m0 + ty * 8 + 2 * ii + 1) * N + n0 + tx * 4] = oo;
    }
}

// ---------------------------------------------------------------------------
// GRU recurrent scan — R13 version (R11 structure + register-carried h).
// ---------------------------------------------------------------------------
#define HQ_HALF 260
#define HQ_P    (2 * HQ_HALF)
#define TXB     2048u

__global__ void __cluster_dims__(4, 1, 1) __launch_bounds__(384, 1)
gru_scan(const float* __restrict__ gates, const float* __restrict__ Whh,
         const float* __restrict__ bhh, float* __restrict__ hout)
{
    __shared__ __align__(16) float hq[2 * HQ_P];
    __shared__ __align__(16) float stag[2][128];
    __shared__ float gh_s[2 * 192];
    __shared__ float bh_s[192];
    __shared__ __align__(8) uint64_t mbar_s[2];

    int tid = threadIdx.x;
    uint32_t rank;
    asm("mov.u32 %0, %%cluster_ctarank;" : "=r"(rank));
    int b0 = (blockIdx.x >> 2) * 2;

    const int row = tid >> 1;
    const int ks  = tid & 1;
    const int g   = row >> 6;
    const int jl  = row & 63;
    const int grow = g * H_ + (int)rank * 64 + jl;

    uint64_t wr[64];
    const uint64_t* wsrc = (const uint64_t*)&Whh[(size_t)grow * H_ + ks * 128];
#pragma unroll
    for (int kk = 0; kk < 64; kk++) wr[kk] = wsrc[kk];

    uint32_t hq_u32   = (uint32_t)__cvta_generic_to_shared(hq);
    uint32_t stag_u32 = (uint32_t)__cvta_generic_to_shared(stag);
    uint32_t mbar_u32 = (uint32_t)__cvta_generic_to_shared(mbar_s);

    if (tid < 192) {
        int gg = tid >> 6, jj = tid & 63;
        bh_s[tid] = bhh[gg * H_ + (int)rank * 64 + jj];
    }
    for (int i = tid; i < 2 * HQ_P; i += 384) hq[i] = 0.0f;
    if (tid == 0) {
        mbar_init_(mbar_u32, 1);
        mbar_init_(mbar_u32 + 8, 1);
        mbar_arm_(mbar_u32 + 8, TXB);
    }
    __syncthreads();
    asm volatile("barrier.cluster.arrive.aligned;" ::: "memory");
    asm volatile("barrier.cluster.wait.aligned;" ::: "memory");

    const uint32_t ks_off = (uint32_t)ks * (HQ_HALF * 4);

    const int jl_e = tid & 63;
    const int bb   = (tid >> 6) & 1;
    const int jg   = (int)rank * 64 + jl_e;
    const int sidx = ((jl_e >> 1) << 2) + bb * 2 + (jl_e & 1);
    const uint32_t dst_off = (rank >> 1) * (HQ_HALF * 4) + (rank & 1) * 512;

    float hprev = 0.0f;
    uint32_t ph = 0;
    for (int t = 0; t < T_; t++) {
        const int buf = t & 1;
        const int nxt = buf ^ 1;

        float xr = 0.f, xz = 0.f, xn = 0.f;
        if (tid < 128) {
            const float* gp = &gates[((size_t)(b0 + bb) * T_ + t) * G3];
            xr = __ldg(gp + jg);
            xz = __ldg(gp + 256 + jg);
            xn = __ldg(gp + 512 + jg);
        }

        if (t) {
            mbar_wait_(mbar_u32 + buf * 8, (ph >> buf) & 1u);
            ph ^= (1u << buf);
        }
        if (tid == 0) mbar_arm_(mbar_u32 + buf * 8, TXB);

        uint32_t hb = hq_u32 + (uint32_t)buf * (HQ_P * 4) + ks_off;
        uint64_t a00 = 0, a01 = 0, a10 = 0, a11 = 0;
#pragma unroll
        for (int kk = 0; kk < 64; kk += 2) {
            uint64_t hx0, hy0, hx1, hy1;
            asm volatile("ld.shared.v2.u64 {%0,%1}, [%2];"
                         : "=l"(hx0), "=l"(hy0) : "r"(hb + kk * 16));
            asm volatile("ld.shared.v2.u64 {%0,%1}, [%2];"
                         : "=l"(hx1), "=l"(hy1) : "r"(hb + kk * 16 + 16));
            fma2_(a00, wr[kk], hx0);
            fma2_(a10, wr[kk], hy0);
            fma2_(a01, wr[kk + 1], hx1);
            fma2_(a11, wr[kk + 1], hy1);
        }
        float s0 = (f2lo_(a00) + f2hi_(a00)) + (f2lo_(a01) + f2hi_(a01));
        float s1 = (f2lo_(a10) + f2hi_(a10)) + (f2lo_(a11) + f2hi_(a11));
        s0 += __shfl_xor_sync(0xffffffffu, s0, 1);
        s1 += __shfl_xor_sync(0xffffffffu, s1, 1);
        if (ks == 0) {
            float bh = bh_s[row];
            gh_s[row]       = s0 + bh;
            gh_s[192 + row] = s1 + bh;
        }
        __syncthreads();

        if (tid < 128) {
            float r = sigmoid_hw_(xr + gh_s[bb * 192 + jl_e]);
            float z = sigmoid_hw_(xz + gh_s[bb * 192 + 64 + jl_e]);
            float n = tanh_hw_(xn + r * gh_s[bb * 192 + 128 + jl_e]);
            float hnew = (1.0f - z) * n + z * hprev;
            hprev = hnew;

            stag[nxt][sidx] = hnew;
            hout[((size_t)(b0 + bb) * T_ + t) * H_ + jg] = hnew;

            asm volatile("bar.sync 1, 128;" ::: "memory");
            if (tid < 4) {
                asm volatile("fence.proxy.async.shared::cta;" ::: "memory");
                uint32_t src = stag_u32 + (uint32_t)nxt * 512;
                uint32_t dst = hq_u32 + (uint32_t)nxt * (HQ_P * 4) + dst_off;
                uint32_t mb  = mbar_u32 + nxt * 8;
                asm volatile(
                    "{\n\t.reg .b32 ra, rb;\n\t"
                    "mapa.shared::cluster.u32 ra, %0, %3;\n\t"
                    "mapa.shared::cluster.u32 rb, %1, %3;\n\t"
                    "cp.async.bulk.shared::cluster.shared::cta."
                    "mbarrier::complete_tx::bytes [ra], [%2], 512, [rb];\n\t}"
                    :: "r"(dst), "r"(mb), "r"(src), "r"((uint32_t)tid) : "memory");
            }
        }
    }

    mbar_wait_(mbar_u32, ph & 1u);
    asm volatile("barrier.cluster.arrive.aligned;" ::: "memory");
    asm volatile("barrier.cluster.wait.aligned;" ::: "memory");
}

// ---------------------------------------------------------------------------
extern "C" void kernel_launch(void* const* d_in, const int* in_sizes, int n_in,
                              void* d_out, int out_size)
{
    const float* x    = (const float*)d_in[0];
    const float* Wih0 = (const float*)d_in[1];
    const float* Whh0 = (const float*)d_in[2];
    const float* bih0 = (const float*)d_in[3];
    const float* bhh0 = (const float*)d_in[4];
    const float* Wih1 = (const float*)d_in[5];
    const float* Whh1 = (const float*)d_in[6];
    const float* bih1 = (const float*)d_in[7];
    const float* bhh1 = (const float*)d_in[8];
    const float* fcw  = (const float*)d_in[9];
    const float* fcb  = (const float*)d_in[10];
    float* out = (float*)d_out;

    float *gates, *h;
    cudaGetSymbolAddress((void**)&gates, g_gates);
    cudaGetSymbolAddress((void**)&h, g_h);

    cudaFuncSetAttribute(gemm_wmma, cudaFuncAttributeMaxDynamicSharedMemorySize,
                         GW_SMEM);

    const int M = B_ * T_;

    // Layer 0: bf16-split tensor GEMM + scan
    gemm_wmma<<<dim3(G3 / 64, M / 128), 256, GW_SMEM>>>(x, Wih0, bih0, gates, G3, I_);
    gru_scan<<<128, 384>>>(gates, Whh0, bhh0, h);

    // Layer 1
    gemm_wmma<<<dim3(G3 / 64, M / 128), 256, GW_SMEM>>>(h, Wih1, bih1, gates, G3, H_);
    gru_scan<<<128, 384>>>(gates, Whh1, bhh1, h);

    // Classifier head (fp32 for final-output precision)
    gemm_nt<<<dim3(C_ / 64, M / 128), dim3(256)>>>(h, fcw, fcb, out, M, C_, H_);
}